// round 17
// baseline (speedup 1.0000x reference)
#include <cuda_runtime.h>
#include <cuda_bf16.h>
#include <cuda_fp16.h>

#define THREADS 256
#define BPSM    6
#define NB      (148 * BPSM)      // 888 blocks, all co-resident
#define NWARP   (THREADS / 32)
#define MAXB    64
#define SLOTS   6
#define CHKG    256               // groups per chunk == THREADS (1 group/thread)
#define GCAP    (SLOTS * CHKG)    // 1536 groups staged: s_z 24.6KB

// ---------------- device scratch (zero-init; no allocations) ----------------
__device__ unsigned d_ag[MAXB];    // max ord(z) | seg==0   (0 => none)
__device__ unsigned d_ap[MAXB];    // max ~ord(z) | seg==1  (0 => none)
__device__ unsigned d_azm[MAXB];   // max ~ord(z) overall
__device__ unsigned d_azx[MAXB];   // max ord(z) overall
__device__ float    d_part[NB];
__device__ unsigned d_c1, d_c2, d_tk;

// branch-free order-preserving float -> uint
__device__ __forceinline__ unsigned ordf(float f) {
    unsigned u = __float_as_uint(f);
    return u ^ ((unsigned)(((int)u) >> 31) | 0x80000000u);
}
__device__ __forceinline__ float deordf(unsigned o) {
    unsigned u = (o & 0x80000000u) ? (o & 0x7FFFFFFFu) : ~o;
    return __uint_as_float(u);
}
__device__ __forceinline__ float packzs(float z, int s) {
    return __uint_as_float((__float_as_uint(z) & ~1u) | (unsigned)(s & 1));
}
#define NEGINF __uint_as_float(0xFF800000u)
#define POSINF __uint_as_float(0x7F800000u)

// focal CE factor: softplus(v) * sigmoid(v)^2. 3 MUFU.
__device__ __forceinline__ float ceTerm(float p0, float p1, int s)
{
    float tgt = s ? p1 : p0;
    float oth = s ? p0 : p1;
    float v   = oth - tgt;
    float nav = fminf(v, -v);                          // -|v|
    float e;  asm("ex2.approx.f32 %0,%1;" : "=f"(e)  : "f"(1.4426950409f * nav));
    float l2; asm("lg2.approx.f32 %0,%1;" : "=f"(l2) : "f"(1.0f + e));
    float sp = fmaxf(v, 0.0f) + 0.69314718056f * l2;   // -log p_t
    float ls = fmaf(2.8853901817f, fminf(v, 0.0f), -2.0f * l2);  // 2*log2(sigmoid)
    float s2; asm("ex2.approx.f32 %0,%1;" : "=f"(s2) : "f"(ls));
    return sp * s2;
}
// gaussian z-weight. 1 MUFU.
__device__ __forceinline__ float wTerm(float z, float mu)
{
    float d  = z - mu;
    float dd = d * d;
    float cf = (d <= 0.0f) ? -72.13475204f : -4.50842200f;   // log2e * {-50, -3.125}
    float ew = (d > 0.8f) ? -3.32192809f : cf * dd;          // log2(0.1) clamp
    float w; asm("ex2.approx.f32 %0,%1;" : "=f"(w) : "f"(ew));
    return w;
}
// full point term; seg bit lives in z's mantissa LSB
__device__ __forceinline__ float termZ(float p0, float p1, float z, float mu)
{
    return ceTerm(p0, p1, __float_as_uint(z) & 1) * wTerm(z, mu);
}
__device__ __forceinline__ float fullTerm(float p0, float p1, int s, float z, float mu)
{
    return ceTerm(p0, p1, s) * wTerm(z, mu);
}

// ================= fused persistent kernel with work stealing =================
template <bool STEAL>
__global__ void __launch_bounds__(THREADS, BPSM) k_fused(
    const float4* __restrict__ pred4, const float* __restrict__ pred,
    const float4* __restrict__ coord4, const float* __restrict__ coord,
    const int4* __restrict__ seg4, const int* __restrict__ segment,
    const int* __restrict__ offset, int n, int B, int nchk, int gpb,
    float* __restrict__ out)
{
    __shared__ float    s_z[GCAP * 4];        // packed z+seg per point (24.6 KB)
    __shared__ int      s_off[MAXB];
    __shared__ float    s_mu[MAXB];
    __shared__ unsigned s_g[MAXB], s_p[MAXB], s_m[MAXB], s_x[MAXB];
    __shared__ float    s_w[NWARP];
    __shared__ int      s_ck[SLOTS];
    __shared__ int      s_cur;
    __shared__ bool     s_last;

    int t = threadIdx.x;
    int bid = blockIdx.x;
    int lane = t & 31, warp = t >> 5;

    for (int j = t; j < B; j += THREADS) {
        s_g[j] = 0u; s_p[j] = 0u; s_m[j] = 0u; s_x[j] = 0u;
        s_off[j] = offset[j];
    }
    __syncthreads();

    int n4 = n >> 2;
    int tail0 = n4 << 2;

    // warp-reduce float stats -> ord-encoded smem atomics (warp-uniform batch b)
    auto wflushF = [&](int b, float lg, float lp, float lzm, float lzx) {
        #pragma unroll
        for (int o = 16; o > 0; o >>= 1) {
            lzm = fminf(lzm, __shfl_xor_sync(~0u, lzm, o));
            lzx = fmaxf(lzx, __shfl_xor_sync(~0u, lzx, o));
            lg  = fmaxf(lg,  __shfl_xor_sync(~0u, lg,  o));
            lp  = fminf(lp,  __shfl_xor_sync(~0u, lp,  o));
        }
        if (lane == 0) {
            atomicMax(&s_m[b], ~ordf(lzm));
            atomicMax(&s_x[b], ordf(lzx));
            if (lg != NEGINF) atomicMax(&s_g[b], ordf(lg));
            if (lp != POSINF) atomicMax(&s_p[b], ~ordf(lp));
        }
    };

    int nck = 0;
    bool ownLast = false;

    // ===================== A1: stolen chunks — stats + stage packed z =====================
    if (STEAL) {
        float lg = NEGINF, lp = POSINF, lzm = POSINF, lzx = NEGINF;
        int curb = -1;

        if (t == 0) s_cur = (int)atomicAdd(&d_tk, 1u);
        __syncthreads();
        int c0 = s_cur;

        while (c0 < nchk && nck < SLOTS) {
            if (t == 0) {
                s_ck[nck] = c0;
                if (nck + 1 < SLOTS) s_cur = (int)atomicAdd(&d_tk, 1u);
            }
            if (c0 == nchk - 1) ownLast = true;

            int gs = c0 * CHKG;
            int ge = min(gs + CHKG, n4);
            int cp0 = gs << 2;
            int cpe = (ge << 2) - 1;
            int cb0 = 0; while (cp0 >= s_off[cb0]) cb0++;
            int cb1 = cb0; while (cpe >= s_off[cb1]) cb1++;
            int g = gs + t;

            if (cb0 == cb1) {
                if (cb0 != curb) {
                    if (curb >= 0) wflushF(curb, lg, lp, lzm, lzx);
                    curb = cb0;
                    lg = NEGINF; lp = POSINF; lzm = POSINF; lzx = NEGINF;
                }
                if (g < ge) {
                    float4 a  = coord4[3 * g + 0];
                    float4 bb = coord4[3 * g + 1];
                    float4 cc = coord4[3 * g + 2];
                    int4   s  = seg4[g];
                    *reinterpret_cast<float4*>(s_z + ((nck * CHKG + t) << 2)) =
                        make_float4(packzs(a.z, s.x), packzs(bb.y, s.y),
                                    packzs(cc.x, s.z), packzs(cc.w, s.w));
                    float z0 = a.z, z1 = bb.y, z2 = cc.x, z3 = cc.w;
                    lzm = fminf(lzm, fminf(fminf(z0, z1), fminf(z2, z3)));
                    lzx = fmaxf(lzx, fmaxf(fmaxf(z0, z1), fmaxf(z2, z3)));
                    lg  = fmaxf(lg, fmaxf(fmaxf(s.x ? NEGINF : z0, s.y ? NEGINF : z1),
                                          fmaxf(s.z ? NEGINF : z2, s.w ? NEGINF : z3)));
                    lp  = fminf(lp, fminf(fminf(s.x ? z0 : POSINF, s.y ? z1 : POSINF),
                                          fminf(s.z ? z2 : POSINF, s.w ? z3 : POSINF)));
                }
            } else if (g < ge) {
                // straddle chunk (<= B-1 per launch): per-point smem atomics
                float4 a  = coord4[3 * g + 0];
                float4 bb = coord4[3 * g + 1];
                float4 cc = coord4[3 * g + 2];
                int4   s  = seg4[g];
                *reinterpret_cast<float4*>(s_z + ((nck * CHKG + t) << 2)) =
                    make_float4(packzs(a.z, s.x), packzs(bb.y, s.y),
                                packzs(cc.x, s.z), packzs(cc.w, s.w));
                int i0 = g << 2;
                float zz[4] = {a.z, bb.y, cc.x, cc.w};
                int   ss[4] = {s.x, s.y, s.z, s.w};
                int b = cb0;
                #pragma unroll
                for (int q = 0; q < 4; q++) {
                    int i = i0 + q;
                    while (i >= s_off[b]) b++;
                    unsigned o = ordf(zz[q]);
                    atomicMax(&s_m[b], ~o);
                    atomicMax(&s_x[b], o);
                    if (ss[q]) atomicMax(&s_p[b], ~o);
                    else       atomicMax(&s_g[b], o);
                }
            }

            nck++;
            __syncthreads();          // chunk consumed; next ticket published
            c0 = (nck < SLOTS) ? s_cur : nchk;
        }
        if (curb >= 0) wflushF(curb, lg, lp, lzm, lzx);

        if (nchk == 0 && bid == 0) ownLast = true;   // degenerate n<4
        if (ownLast) {
            for (int i = tail0 + t; i < n; i += THREADS) {
                int b = 0; while (i >= s_off[b]) b++;
                unsigned o = ordf(coord[3 * i + 2]);
                atomicMax(&s_m[b], ~o);
                atomicMax(&s_x[b], o);
                if (segment[i]) atomicMax(&s_p[b], ~o);
                else            atomicMax(&s_g[b], o);
            }
        }
    } else {
        // static fallback (large n): stats only, no staging
        int g0 = bid * gpb;
        int g1 = min(g0 + gpb, n4);
        bool isLast = (bid == NB - 1);
        if (isLast) ownLast = true;
        if (g0 < g1) {
            int cp0 = g0 << 2;
            int cpe = isLast ? (n - 1) : ((g1 << 2) - 1);
            int b0 = 0; while (cp0 >= s_off[b0]) b0++;
            int b1 = b0; while (cpe >= s_off[b1]) b1++;
            if (b0 == b1) {
                float lg = NEGINF, lp = POSINF, lzm = POSINF, lzx = NEGINF;
                for (int g = g0 + t; g < g1; g += THREADS) {
                    float4 a  = coord4[3 * g + 0];
                    float4 bb = coord4[3 * g + 1];
                    float4 cc = coord4[3 * g + 2];
                    int4   s  = seg4[g];
                    float z0 = a.z, z1 = bb.y, z2 = cc.x, z3 = cc.w;
                    lzm = fminf(lzm, fminf(fminf(z0, z1), fminf(z2, z3)));
                    lzx = fmaxf(lzx, fmaxf(fmaxf(z0, z1), fmaxf(z2, z3)));
                    lg  = fmaxf(lg, fmaxf(fmaxf(s.x ? NEGINF : z0, s.y ? NEGINF : z1),
                                          fmaxf(s.z ? NEGINF : z2, s.w ? NEGINF : z3)));
                    lp  = fminf(lp, fminf(fminf(s.x ? z0 : POSINF, s.y ? z1 : POSINF),
                                          fminf(s.z ? z2 : POSINF, s.w ? z3 : POSINF)));
                }
                wflushF(b0, lg, lp, lzm, lzx);
            } else {
                for (int g = g0 + t; g < g1; g += THREADS) {
                    float4 a  = coord4[3 * g + 0];
                    float4 bb = coord4[3 * g + 1];
                    float4 cc = coord4[3 * g + 2];
                    int4   s  = seg4[g];
                    int i0 = g << 2;
                    float zz[4] = {a.z, bb.y, cc.x, cc.w};
                    int   ss[4] = {s.x, s.y, s.z, s.w};
                    int b = b0;
                    #pragma unroll
                    for (int q = 0; q < 4; q++) {
                        int i = i0 + q;
                        while (i >= s_off[b]) b++;
                        unsigned o = ordf(zz[q]);
                        atomicMax(&s_m[b], ~o);
                        atomicMax(&s_x[b], o);
                        if (ss[q]) atomicMax(&s_p[b], ~o);
                        else       atomicMax(&s_g[b], o);
                    }
                }
            }
        }
        if (ownLast) {
            for (int i = tail0 + t; i < n; i += THREADS) {
                int b = 0; while (i >= s_off[b]) b++;
                unsigned o = ordf(coord[3 * i + 2]);
                atomicMax(&s_m[b], ~o);
                atomicMax(&s_x[b], o);
                if (segment[i]) atomicMax(&s_p[b], ~o);
                else            atomicMax(&s_g[b], o);
            }
        }
    }

    __syncthreads();
    for (int j = t; j < B; j += THREADS) {
        if (s_g[j]) atomicMax(&d_ag[j],  s_g[j]);
        if (s_p[j]) atomicMax(&d_ap[j],  s_p[j]);
        if (s_m[j]) atomicMax(&d_azm[j], s_m[j]);
        if (s_x[j]) atomicMax(&d_azx[j], s_x[j]);
    }
    __threadfence();
    __syncthreads();

    // ===================== barrier + mu (stealing => tiny straggler spread) =====================
    if (t == 0) {
        atomicAdd(&d_c1, 1u);
        while (atomicAdd(&d_c1, 0u) < (unsigned)NB) { __nanosleep(64); }
    }
    __syncthreads();
    __threadfence();
    for (int j = t; j < B; j += THREADS) {
        unsigned ag  = __ldcg(&d_ag[j]);
        unsigned ap  = __ldcg(&d_ap[j]);
        unsigned azm = __ldcg(&d_azm[j]);
        unsigned azx = __ldcg(&d_azx[j]);
        float g = ag ? deordf(ag)  : deordf(~azm);
        float p = ap ? deordf(~ap) : deordf(azx);
        s_mu[j] = g + (p - g) * 0.5f;
    }
    __syncthreads();

    // ===================== phase B: pred from gmem + staged z =====================
    float acc = 0.0f;
    if (STEAL) {
        for (int k = 0; k < nck; k++) {
            int c = s_ck[k];
            int gs = c * CHKG;
            int ge = min(gs + CHKG, n4);
            int g = gs + t;
            if (g < ge) {
                float4 pa = pred4[2 * g + 0];
                float4 pb = pred4[2 * g + 1];
                float4 zv = *reinterpret_cast<const float4*>(s_z + ((k * CHKG + t) << 2));

                int cp0 = gs << 2;
                int cpe = (ge << 2) - 1;
                int cb0 = 0; while (cp0 >= s_off[cb0]) cb0++;
                int cb1 = cb0; while (cpe >= s_off[cb1]) cb1++;

                float m0, m1, m2, m3;
                if (cb0 == cb1) {
                    m0 = m1 = m2 = m3 = s_mu[cb0];
                } else {
                    int i0 = g << 2;
                    int b = cb0; while (i0 >= s_off[b]) b++;
                    int q1 = b;  while (i0 + 1 >= s_off[q1]) q1++;
                    int q2 = q1; while (i0 + 2 >= s_off[q2]) q2++;
                    int q3 = q2; while (i0 + 3 >= s_off[q3]) q3++;
                    m0 = s_mu[b]; m1 = s_mu[q1]; m2 = s_mu[q2]; m3 = s_mu[q3];
                }
                acc += termZ(pa.x, pa.y, zv.x, m0);
                acc += termZ(pa.z, pa.w, zv.y, m1);
                acc += termZ(pb.x, pb.y, zv.z, m2);
                acc += termZ(pb.z, pb.w, zv.w, m3);
            }
        }
    } else {
        int g0 = bid * gpb;
        int g1 = min(g0 + gpb, n4);
        if (g0 < g1) {
            int cp0 = g0 << 2;
            int b0 = 0; while (cp0 >= s_off[b0]) b0++;
            int cur = b0;
            for (int g = g0 + t; g < g1; g += THREADS) {
                float4 pa = pred4[2 * g + 0];
                float4 pb = pred4[2 * g + 1];
                float4 a  = coord4[3 * g + 0];
                float4 bb = coord4[3 * g + 1];
                float4 cc = coord4[3 * g + 2];
                int4   s  = seg4[g];
                int i0 = g << 2;
                int b = cur; while (i0 >= s_off[b]) b++;
                int q1 = b;  while (i0 + 1 >= s_off[q1]) q1++;
                int q2 = q1; while (i0 + 2 >= s_off[q2]) q2++;
                int q3 = q2; while (i0 + 3 >= s_off[q3]) q3++;
                acc += fullTerm(pa.x, pa.y, s.x, a.z,  s_mu[b]);
                acc += fullTerm(pa.z, pa.w, s.y, bb.y, s_mu[q1]);
                acc += fullTerm(pb.x, pb.y, s.z, cc.x, s_mu[q2]);
                acc += fullTerm(pb.z, pb.w, s.w, cc.w, s_mu[q3]);
            }
        }
    }
    if (ownLast) {
        for (int i = tail0 + t; i < n; i += THREADS) {
            int b = 0; while (i >= s_off[b]) b++;
            acc += fullTerm(pred[2 * i], pred[2 * i + 1], segment[i],
                            coord[3 * i + 2], s_mu[b]);
        }
    }

    #pragma unroll
    for (int o = 16; o > 0; o >>= 1) acc += __shfl_xor_sync(~0u, acc, o);
    if (lane == 0) s_w[warp] = acc;
    __syncthreads();
    if (t == 0) {
        float tot = 0.0f;
        #pragma unroll
        for (int w = 0; w < NWARP; w++) tot += s_w[w];
        d_part[bid] = tot;
        __threadfence();
        s_last = (atomicAdd(&d_c2, 1u) == NB - 1);
    }
    __syncthreads();

    if (s_last) {
        double* s_d = reinterpret_cast<double*>(s_z);
        double da = 0.0;
        for (int i = t; i < NB; i += THREADS) da += (double)d_part[i];
        s_d[t] = da;
        __syncthreads();
        for (int s = THREADS / 2; s > 0; s >>= 1) {
            if (t < s) s_d[t] += s_d[t + s];
            __syncthreads();
        }
        for (int j = t; j < B; j += THREADS) {
            d_ag[j] = 0u; d_ap[j] = 0u; d_azm[j] = 0u; d_azx[j] = 0u;
        }
        if (t == 0) {
            out[0] = (float)(s_d[0] / (double)n);
            d_c1 = 0u; d_c2 = 0u; d_tk = 0u;
        }
    }
}

// ---------------- launch ----------------
extern "C" void kernel_launch(void* const* d_in, const int* in_sizes, int n_in,
                              void* d_out, int out_size)
{
    const float* pred    = (const float*)d_in[0];
    const float* coord   = (const float*)d_in[1];
    const int*   segment = (const int*)d_in[2];
    const int*   offset  = (const int*)d_in[3];
    int n = in_sizes[2];
    int B = in_sizes[3];
    if (B > MAXB) B = MAXB;
    if (B < 1) B = 1;

    int n4 = n >> 2;
    int nchk = (n4 + CHKG - 1) / CHKG;
    int gpb = (n4 + NB - 1) / NB;
    if (gpb < 1) gpb = 1;
    bool steal = (nchk <= NB * SLOTS);

    if (steal) {
        k_fused<true><<<NB, THREADS>>>((const float4*)pred, pred,
                                       (const float4*)coord, coord,
                                       (const int4*)segment, segment,
                                       offset, n, B, nchk, gpb, (float*)d_out);
    } else {
        k_fused<false><<<NB, THREADS>>>((const float4*)pred, pred,
                                        (const float4*)coord, coord,
                                        (const int4*)segment, segment,
                                        offset, n, B, nchk, gpb, (float*)d_out);
    }
}